// round 10
// baseline (speedup 1.0000x reference)
#include <cuda_runtime.h>

// Problem constants
#define Bq    256
#define Tq    512
#define INq   4
#define Mq    3
#define Dq    256
#define NSq   64
#define Hq    128
#define PAIRS 768      // Mq*Dq
#define G3q   384      // 3*Hq
#define NTHR  256
#define NCTA  128      // 2 batches per CTA
#define BT_TOT (Bq*Tq)

struct __align__(16) Smem {
    float sST[NSq * PAIRS];   // S transposed: [n][pair]
    float sK[2 * PAIRS];      // K values: [b][pair]
    float sNS[2 * 192];       // new_state: [b][m*64+n]
    float sGh[2 * G3q];       // gh: [b][col]
    float sH[2 * Hq];         // hidden state
    float sS[2 * NSq];        // recurrent state s
    float sWih[4 * G3q];      // W_ih row-major
    float sBih[G3q];
    float sBhh[G3q];
    float sWdT[3 * 128];      // Wd transposed, padded (col 127 = 0)
    float sBd[4];
    float sX[8];              // x_t for both batches
    float sY[4];
    float sErr[4];
    float sEnc[8];            // encoded max: [b*3+m]
    float sEncW[8 * 8];       // per-warp max partials
    float sLog[8];            // gate logits
    float sGate[8];           // gate (carried)
};

// Precomputed weight transforms
__device__ __align__(16) float g_ST[NSq * PAIRS];       // [n][pair]
__device__ __align__(16) float g_AT[Mq * NSq * Dq];     // [m][n][d]
__device__ __align__(16) float g_C[PAIRS];              // -0.5*(|U_p|^2 + |S_p|^2)

__global__ void prep_kernel(const float* __restrict__ U,
                            const float* __restrict__ S,
                            const float* __restrict__ A) {
    int p = blockIdx.x * blockDim.x + threadIdx.x;
    if (p >= PAIRS) return;
    int m = p / Dq, d = p % Dq;
    float cs = 0.f;
    for (int n = 0; n < NSq; n++) {
        float v = S[p * NSq + n];
        cs += v * v;
        g_ST[n * PAIRS + p] = v;
        g_AT[(m * NSq + n) * Dq + d] = A[p * NSq + n];
    }
    float cu = 0.f;
    for (int i = 0; i < INq; i++) { float u = U[p * INq + i]; cu += u * u; }
    g_C[p] = -0.5f * (cu + cs);
}

// Precise nonlinearities for the recurrent-critical pointwise path (cheap: few threads)
__device__ __forceinline__ float sigmoid_precise(float v) {
    return 1.f / (1.f + expf(-v));
}

__global__ void __launch_bounds__(NTHR, 1)
scan_kernel(const float* __restrict__ x, const float* __restrict__ y,
            const float* __restrict__ U,
            const float* __restrict__ Whh,
            const float* __restrict__ Wd, const float* __restrict__ bd,
            const float* __restrict__ Wih,
            const float* __restrict__ bih, const float* __restrict__ bhh,
            float* __restrict__ out) {
    extern __shared__ float smraw[];
    Smem* sm = reinterpret_cast<Smem*>(smraw);
    const int tid  = threadIdx.x;
    const int wid  = tid >> 5;
    const int lane = tid & 31;
    const int b0   = blockIdx.x * 2;

    // Per-thread persistent constants: U rows + C for this thread's 3 pairs
    float Ur[3][4], Cr[3];
#pragma unroll
    for (int pp = 0; pp < 3; pp++) {
        int p = tid + pp * 256;
        Cr[pp] = g_C[p];
#pragma unroll
        for (int i = 0; i < 4; i++) Ur[pp][i] = U[p * 4 + i];
    }

    // ---- one-time smem init ----
    {
        const float4* src = reinterpret_cast<const float4*>(g_ST);
        float4* dst = reinterpret_cast<float4*>(sm->sST);
        for (int i = tid; i < (NSq * PAIRS) / 4; i += NTHR) dst[i] = src[i];
    }
    for (int i = tid; i < 4 * G3q; i += NTHR) sm->sWih[i] = Wih[i];
    for (int i = tid; i < G3q; i += NTHR) { sm->sBih[i] = bih[i]; sm->sBhh[i] = bhh[i]; }
    // FIX (R8 bug): 384 entries need a strided loop over 256 threads; previously
    // sWdT[256..383] (all of Wd row m=2) was uninitialized smem garbage.
    for (int i = tid; i < 3 * 128; i += NTHR) {
        int m = i >> 7, j = i & 127;
        sm->sWdT[m * 128 + j] = (j < 127) ? Wd[j * 3 + m] : 0.f;
    }
    if (tid < 3) sm->sBd[tid] = bd[tid];
    if (tid < 128) sm->sS[tid] = 0.f;
    sm->sH[tid] = 0.f;  // 256 threads cover 2*128
    if (tid < 8) {
        int mm = tid & 3;
        sm->sGate[tid] = (mm == 0) ? 0.3333f : (mm == 1) ? 0.3333f : (mm == 2) ? 0.3334f : 0.f;
    }
    if (tid < 2) sm->sErr[tid] = 1.f;
    // preload t=0
    if (tid < 8) {
        int b = tid >> 2, i = tid & 3;
        sm->sX[b * 4 + i] = x[(size_t)(b0 + b) * Tq * INq + i];
    }
    if (tid >= 8 && tid < 10) {
        int b = tid - 8;
        sm->sY[b] = y[(size_t)(b0 + b) * Tq];
    }
    __syncthreads();

    for (int t = 0; t < Tq; t++) {
        // ================= Region 1: K = exp(C + x.U + s.S - 0.5|x|^2 - 0.5|s|^2)
        float a00 = 0.f, a01 = 0.f, a10 = 0.f, a11 = 0.f, a20 = 0.f, a21 = 0.f;
        float q0 = 0.f, q1 = 0.f;
#pragma unroll 8
        for (int n = 0; n < NSq; n++) {
            float sv0 = sm->sS[n];
            float sv1 = sm->sS[64 + n];
            q0 += sv0 * sv0;
            q1 += sv1 * sv1;
            float w0 = sm->sST[n * PAIRS + tid];
            float w1 = sm->sST[n * PAIRS + tid + 256];
            float w2 = sm->sST[n * PAIRS + tid + 512];
            a00 += sv0 * w0; a01 += sv1 * w0;
            a10 += sv0 * w1; a11 += sv1 * w1;
            a20 += sv0 * w2; a21 += sv1 * w2;
        }
        float xa[4], xb[4];
#pragma unroll
        for (int i = 0; i < 4; i++) { xa[i] = sm->sX[i]; xb[i] = sm->sX[4 + i]; }
        float xq0 = xa[0]*xa[0] + xa[1]*xa[1] + xa[2]*xa[2] + xa[3]*xa[3];
        float xq1 = xb[0]*xb[0] + xb[1]*xb[1] + xb[2]*xb[2] + xb[3]*xb[3];
        float base0 = -0.5f * (xq0 + q0);
        float base1 = -0.5f * (xq1 + q1);
        float accs0[3] = {a00, a10, a20};
        float accs1[3] = {a01, a11, a21};
#pragma unroll
        for (int pp = 0; pp < 3; pp++) {
            float xu0 = xa[0]*Ur[pp][0] + xa[1]*Ur[pp][1] + xa[2]*Ur[pp][2] + xa[3]*Ur[pp][3];
            float xu1 = xb[0]*Ur[pp][0] + xb[1]*Ur[pp][1] + xb[2]*Ur[pp][2] + xb[3]*Ur[pp][3];
            float k0 = __expf(Cr[pp] + base0 + xu0 + accs0[pp]);
            float k1 = __expf(Cr[pp] + base1 + xu1 + accs1[pp]);
            sm->sK[pp * 256 + tid]         = k0;
            sm->sK[PAIRS + pp * 256 + tid] = k1;
            float v0 = k0, v1 = k1;
#pragma unroll
            for (int off = 16; off; off >>= 1) {
                v0 = fmaxf(v0, __shfl_xor_sync(0xffffffffu, v0, off));
                v1 = fmaxf(v1, __shfl_xor_sync(0xffffffffu, v1, off));
            }
            if (lane == 0) {
                sm->sEncW[wid * 8 + pp]     = v0;
                sm->sEncW[wid * 8 + 3 + pp] = v1;
            }
        }
        __syncthreads();

        // ================= Region 2: encoded-final + gh (GRU input GEMM) + new_state
        if (tid < 6) {
            float v = sm->sEncW[tid];
#pragma unroll
            for (int w = 1; w < 8; w++) v = fmaxf(v, sm->sEncW[w * 8 + tid]);
            sm->sEnc[tid] = v;   // slot = b*3 + m
        }
        // gh = h @ W_hh + b_hh  (both batches share weight loads)
        {
            int ncol = (tid < 128) ? 2 : 1;
            for (int cc = 0; cc < ncol; cc++) {
                int c = tid + cc * 256;
                float acc0 = sm->sBhh[c];
                float acc1 = acc0;
                const float* W = Whh + c;
#pragma unroll 16
                for (int k = 0; k < Hq; k++) {
                    float w = __ldg(W + k * G3q);
                    acc0 += sm->sH[k] * w;
                    acc1 += sm->sH[128 + k] * w;
                }
                sm->sGh[c]       = acc0;
                sm->sGh[G3q + c] = acc1;
            }
        }
        // new_state[b][m][n] = sum_d K[b][m][d] * A[m][d][n]; warp per (m,n), lanes span d
        {
#pragma unroll 2
            for (int j = 0; j < 24; j++) {
                int r = wid * 24 + j;
                int m = r >> 6, n = r & 63;
                const float4* Arow = reinterpret_cast<const float4*>(g_AT + (m * NSq + n) * Dq);
                const float4* K0   = reinterpret_cast<const float4*>(sm->sK + m * Dq);
                const float4* K1   = reinterpret_cast<const float4*>(sm->sK + PAIRS + m * Dq);
                float4 av0 = __ldg(Arow + lane);
                float4 av1 = __ldg(Arow + 32 + lane);
                float4 k0a = K0[lane],      k0b = K0[32 + lane];
                float4 k1a = K1[lane],      k1b = K1[32 + lane];
                float acc0 = av0.x*k0a.x + av0.y*k0a.y + av0.z*k0a.z + av0.w*k0a.w
                           + av1.x*k0b.x + av1.y*k0b.y + av1.z*k0b.z + av1.w*k0b.w;
                float acc1 = av0.x*k1a.x + av0.y*k1a.y + av0.z*k1a.z + av0.w*k1a.w
                           + av1.x*k1b.x + av1.y*k1b.y + av1.z*k1b.z + av1.w*k1b.w;
#pragma unroll
                for (int off = 16; off; off >>= 1) {
                    acc0 += __shfl_xor_sync(0xffffffffu, acc0, off);
                    acc1 += __shfl_xor_sync(0xffffffffu, acc1, off);
                }
                if (lane == 0) {
                    sm->sNS[m * 64 + n]       = acc0;
                    sm->sNS[192 + m * 64 + n] = acc1;
                }
            }
        }
        __syncthreads();

        // ================= Region 3: GRU elementwise (+ tiny gi GEMM inline)
        {
            int b = tid >> 7, j = tid & 127;
            float e0 = sm->sEnc[b * 3 + 0];
            float e1 = sm->sEnc[b * 3 + 1];
            float e2 = sm->sEnc[b * 3 + 2];
            float er = sm->sErr[b];
            float gir = sm->sBih[j]
                      + e0 * sm->sWih[j]            + e1 * sm->sWih[G3q + j]
                      + e2 * sm->sWih[2*G3q + j]    + er * sm->sWih[3*G3q + j];
            float giz = sm->sBih[128 + j]
                      + e0 * sm->sWih[128 + j]          + e1 * sm->sWih[G3q + 128 + j]
                      + e2 * sm->sWih[2*G3q + 128 + j]  + er * sm->sWih[3*G3q + 128 + j];
            float gin = sm->sBih[256 + j]
                      + e0 * sm->sWih[256 + j]          + e1 * sm->sWih[G3q + 256 + j]
                      + e2 * sm->sWih[2*G3q + 256 + j]  + er * sm->sWih[3*G3q + 256 + j];
            float ghr = sm->sGh[b * G3q + j];
            float ghz = sm->sGh[b * G3q + 128 + j];
            float ghn = sm->sGh[b * G3q + 256 + j];
            float rr = sigmoid_precise(gir + ghr);
            float zz = sigmoid_precise(giz + ghz);
            float nn = tanhf(gin + rr * ghn);
            float hold = sm->sH[b * 128 + j];
            sm->sH[b * 128 + j] = (1.f - zz) * nn + zz * hold;
        }
        __syncthreads();

        // ================= Region 4: gate logits = h_new[:127] @ Wd + bd
        if (wid < 6) {
            int b = wid / 3, m = wid % 3;
            float acc = 0.f;
#pragma unroll
            for (int k = 0; k < 4; k++) {
                int j = lane + 32 * k;
                acc += sm->sH[b * 128 + j] * sm->sWdT[m * 128 + j];  // j==127 weight is 0
            }
#pragma unroll
            for (int off = 16; off; off >>= 1)
                acc += __shfl_xor_sync(0xffffffffu, acc, off);
            if (lane == 0) sm->sLog[b * 4 + m] = acc + sm->sBd[m];
        }
        __syncthreads();

        // ================= Region 5: softmax + theta-mix + penalty (1 thread per batch)
        if (tid < 2) {
            int b = tid, bb = b0 + b;
            float l0 = sm->sLog[b * 4], l1 = sm->sLog[b * 4 + 1], l2 = sm->sLog[b * 4 + 2];
            float mx = fmaxf(l0, fmaxf(l1, l2));
            float e0 = expf(l0 - mx), e1 = expf(l1 - mx), e2 = expf(l2 - mx);
            float inv = 1.f / (e0 + e1 + e2);
            float theta = sigmoid_precise(sm->sH[b * 128 + 127]);
            float omt = 1.f - theta;
            float g0 = e0 * inv * theta + sm->sGate[b * 4]     * omt;
            float g1 = e1 * inv * theta + sm->sGate[b * 4 + 1] * omt;
            float g2 = e2 * inv * theta + sm->sGate[b * 4 + 2] * omt;
            sm->sGate[b * 4]     = g0;
            sm->sGate[b * 4 + 1] = g1;
            sm->sGate[b * 4 + 2] = g2;
            float pen = g0 * (1.f - g0) + g1 * (1.f - g1) + g2 * (1.f - g2);
            out[BT_TOT + (size_t)bb * Tq + t] = pen;
        }
        __syncthreads();

        // ================= Region 6: s_new = gate . new_state; outputs; next-x preload
        if (tid < 128) {
            int b = tid >> 6, n = tid & 63;
            float g0 = sm->sGate[b * 4], g1 = sm->sGate[b * 4 + 1], g2 = sm->sGate[b * 4 + 2];
            float sv = g0 * sm->sNS[b * 192 + n]
                     + g1 * sm->sNS[b * 192 + 64 + n]
                     + g2 * sm->sNS[b * 192 + 128 + n];
            sm->sS[b * 64 + n] = sv;
            if (n == 63) {
                int bb = b0 + b;
                out[(size_t)bb * Tq + t] = sv;       // pred
                sm->sErr[b] = sv - sm->sY[b];
            }
        } else if (t + 1 < Tq) {
            int q = tid - 128;
            if (q < 8) {
                int b = q >> 2, i = q & 3;
                sm->sX[b * 4 + i] = x[(size_t)(b0 + b) * Tq * INq + (size_t)(t + 1) * INq + i];
            } else if (q < 10) {
                int b = q - 8;
                sm->sY[b] = y[(size_t)(b0 + b) * Tq + (t + 1)];
            }
        }
        __syncthreads();
    }
}

extern "C" void kernel_launch(void* const* d_in, const int* in_sizes, int n_in,
                              void* d_out, int out_size) {
    const float* x   = (const float*)d_in[0];
    const float* y   = (const float*)d_in[1];
    const float* U   = (const float*)d_in[2];
    const float* S   = (const float*)d_in[3];
    const float* A   = (const float*)d_in[4];
    const float* Wih = (const float*)d_in[5];
    const float* Whh = (const float*)d_in[6];
    const float* bih = (const float*)d_in[7];
    const float* bhh = (const float*)d_in[8];
    const float* Wd  = (const float*)d_in[9];
    const float* bd  = (const float*)d_in[10];
    float* out = (float*)d_out;

    cudaFuncSetAttribute(scan_kernel, cudaFuncAttributeMaxDynamicSharedMemorySize,
                         (int)sizeof(Smem));

    prep_kernel<<<3, 256>>>(U, S, A);
    scan_kernel<<<NCTA, NTHR, sizeof(Smem)>>>(x, y, U, Whh, Wd, bd, Wih, bih, bhh, out);
}

// round 12
// speedup vs baseline: 2.0083x; 2.0083x over previous
#include <cuda_runtime.h>

// Problem constants
#define Bq    256
#define Tq    512
#define INq   4
#define PAIRS 768      // M*D
#define NSq   64
#define Hq    128
#define G3q   384      // 3*H
#define NTHR  384
#define NCTA  128      // 2 batches per CTA
#define BT_TOT (Bq*Tq)
#define WREG  96       // W_hh rows cached in registers

struct __align__(16) Smem {
    float sST[NSq * PAIRS];   // S transposed: [n][p]
    float sK[2 * PAIRS];      // K values: [b][p] (float2 pairs (2t,2t+1))
    float sGh[2 * G3q];       // gh: [b][col]
    float sH[2 * Hq];         // hidden state
    float sS[2 * NSq];        // recurrent state s
    float sWih[4 * G3q];      // W_ih row-major
    float sBih[G3q];
    float sBhh[G3q];
    float sWdT[3 * Hq];       // Wd transposed, padded (col 127 = 0)
    float sRed[12 * 128];     // s_new partials: [warp][b*64+n]
    float sEncW[32];          // per-warp K max: [w*2+b] (w<12)
    float sQpart[4];          // warp partials of |s|^2
    float sBd[4];
    float sX[8];              // x_t both batches
    float sY[4];
    float sErr[4];
    float sGate[8];           // gate (carried): [b*4+m]
};

// Precomputed weight transforms
__device__ __align__(16) float g_ST[NSq * PAIRS];   // [n][p]
__device__ __align__(16) float g_C[PAIRS];          // -0.5*(|U_p|^2+|S_p|^2)

__global__ void prep_kernel(const float* __restrict__ U,
                            const float* __restrict__ S) {
    int p = blockIdx.x * blockDim.x + threadIdx.x;
    if (p >= PAIRS) return;
    float cs = 0.f;
    for (int n = 0; n < NSq; n++) {
        float v = S[p * NSq + n];
        cs += v * v;
        g_ST[n * PAIRS + p] = v;
    }
    float cu = 0.f;
    for (int i = 0; i < INq; i++) { float u = U[p * INq + i]; cu += u * u; }
    g_C[p] = -0.5f * (cu + cs);
}

__device__ __forceinline__ float sigmoid_precise(float v) {
    return 1.f / (1.f + expf(-v));
}

__global__ void __launch_bounds__(NTHR, 1)
scan_kernel(const float* __restrict__ x, const float* __restrict__ y,
            const float* __restrict__ U, const float* __restrict__ A,
            const float* __restrict__ Whh,
            const float* __restrict__ Wd, const float* __restrict__ bd,
            const float* __restrict__ Wih,
            const float* __restrict__ bih, const float* __restrict__ bhh,
            float* __restrict__ out) {
    extern __shared__ float smraw[];
    Smem* sm = reinterpret_cast<Smem*>(smraw);
    const int tid  = threadIdx.x;
    const int wid  = tid >> 5;
    const int lane = tid & 31;
    const int b0   = blockIdx.x * 2;

    // ---- persistent registers: W_hh column (rows 0..WREG-1) for col = tid
    float whh[WREG];
#pragma unroll
    for (int k = 0; k < WREG; k++) whh[k] = Whh[k * G3q + tid];

    // U rows + C for this thread's two adjacent pairs p0=2t, p1=2t+1
    const int p0 = 2 * tid, p1 = 2 * tid + 1;
    float Ua[4], Ub[4];
#pragma unroll
    for (int i = 0; i < 4; i++) { Ua[i] = U[p0 * 4 + i]; Ub[i] = U[p1 * 4 + i]; }
    const float C0 = g_C[p0], C1 = g_C[p1];

    // ---- one-time smem init ----
    {
        const float4* src = reinterpret_cast<const float4*>(g_ST);
        float4* dst = reinterpret_cast<float4*>(sm->sST);
        for (int i = tid; i < (NSq * PAIRS) / 4; i += NTHR) dst[i] = src[i];
    }
    for (int i = tid; i < 4 * G3q; i += NTHR) sm->sWih[i] = Wih[i];
    for (int i = tid; i < G3q; i += NTHR) { sm->sBih[i] = bih[i]; sm->sBhh[i] = bhh[i]; }
    for (int i = tid; i < 3 * Hq; i += NTHR) {
        int m = i >> 7, j = i & 127;
        sm->sWdT[m * 128 + j] = (j < 127) ? Wd[j * 3 + m] : 0.f;
    }
    if (tid < 4) sm->sBd[tid] = (tid < 3) ? bd[tid] : 0.f;
    for (int i = tid; i < 2 * NSq; i += NTHR) sm->sS[i] = 0.f;
    for (int i = tid; i < 2 * Hq; i += NTHR) sm->sH[i] = 0.f;
    if (tid < 8) {
        int mm = tid & 3;
        sm->sGate[tid] = (mm == 0) ? 0.3333f : (mm == 1) ? 0.3333f : (mm == 2) ? 0.3334f : 0.f;
    }
    if (tid < 2) sm->sErr[tid] = 1.f;
    if (tid < 4) sm->sQpart[tid] = 0.f;
    if (tid < 8) {
        int b = tid >> 2, i = tid & 3;
        sm->sX[b * 4 + i] = x[(size_t)(b0 + b) * Tq * INq + i];
    }
    if (tid >= 8 && tid < 10) {
        int b = tid - 8;
        sm->sY[b] = y[(size_t)(b0 + b) * Tq];
    }
    __syncthreads();

    for (int t = 0; t < Tq; t++) {
        // ===== Region A: K = exp(C + base + x.U + s.S), per-warp enc max, gh GEMV =====
        {
            float q0 = sm->sQpart[0] + sm->sQpart[1];
            float q1 = sm->sQpart[2] + sm->sQpart[3];
            float xa0 = sm->sX[0], xa1 = sm->sX[1], xa2 = sm->sX[2], xa3 = sm->sX[3];
            float xb0 = sm->sX[4], xb1 = sm->sX[5], xb2 = sm->sX[6], xb3 = sm->sX[7];
            float base0 = -0.5f * (xa0*xa0 + xa1*xa1 + xa2*xa2 + xa3*xa3 + q0);
            float base1 = -0.5f * (xb0*xb0 + xb1*xb1 + xb2*xb2 + xb3*xb3 + q1);

            float a00 = 0.f, a01 = 0.f, a10 = 0.f, a11 = 0.f;
            const float2* W2 = reinterpret_cast<const float2*>(sm->sST);
#pragma unroll
            for (int n = 0; n < NSq; n += 4) {
                float4 sv0 = *reinterpret_cast<const float4*>(&sm->sS[n]);
                float4 sv1 = *reinterpret_cast<const float4*>(&sm->sS[64 + n]);
                float2 w0 = W2[(n + 0) * 384 + tid];
                float2 w1 = W2[(n + 1) * 384 + tid];
                float2 w2 = W2[(n + 2) * 384 + tid];
                float2 w3 = W2[(n + 3) * 384 + tid];
                a00 += sv0.x*w0.x + sv0.y*w1.x + sv0.z*w2.x + sv0.w*w3.x;
                a10 += sv0.x*w0.y + sv0.y*w1.y + sv0.z*w2.y + sv0.w*w3.y;
                a01 += sv1.x*w0.x + sv1.y*w1.x + sv1.z*w2.x + sv1.w*w3.x;
                a11 += sv1.x*w0.y + sv1.y*w1.y + sv1.z*w2.y + sv1.w*w3.y;
            }
            float xu00 = xa0*Ua[0] + xa1*Ua[1] + xa2*Ua[2] + xa3*Ua[3];
            float xu01 = xb0*Ua[0] + xb1*Ua[1] + xb2*Ua[2] + xb3*Ua[3];
            float xu10 = xa0*Ub[0] + xa1*Ub[1] + xa2*Ub[2] + xa3*Ub[3];
            float xu11 = xb0*Ub[0] + xb1*Ub[1] + xb2*Ub[2] + xb3*Ub[3];
            float k00 = __expf(C0 + base0 + xu00 + a00);   // pair p0, batch 0
            float k01 = __expf(C0 + base1 + xu01 + a01);   // pair p0, batch 1
            float k10 = __expf(C1 + base0 + xu10 + a10);   // pair p1, batch 0
            float k11 = __expf(C1 + base1 + xu11 + a11);   // pair p1, batch 1
            reinterpret_cast<float2*>(sm->sK)[tid]       = make_float2(k00, k10);
            reinterpret_cast<float2*>(sm->sK)[384 + tid] = make_float2(k01, k11);
            // per-warp K max (m is uniform within a warp: m = wid>>2)
            float v0 = fmaxf(k00, k10), v1 = fmaxf(k01, k11);
#pragma unroll
            for (int off = 16; off; off >>= 1) {
                v0 = fmaxf(v0, __shfl_xor_sync(0xffffffffu, v0, off));
                v1 = fmaxf(v1, __shfl_xor_sync(0xffffffffu, v1, off));
            }
            if (lane == 0) { sm->sEncW[wid * 2] = v0; sm->sEncW[wid * 2 + 1] = v1; }

            // gh = h @ W_hh + b_hh : col = tid, register-cached rows + L2 tail
            float acc0 = sm->sBhh[tid];
            float acc1 = acc0;
#pragma unroll
            for (int k = 0; k < WREG; k += 4) {
                float4 h0 = *reinterpret_cast<const float4*>(&sm->sH[k]);
                float4 h1 = *reinterpret_cast<const float4*>(&sm->sH[128 + k]);
                acc0 += h0.x*whh[k] + h0.y*whh[k+1] + h0.z*whh[k+2] + h0.w*whh[k+3];
                acc1 += h1.x*whh[k] + h1.y*whh[k+1] + h1.z*whh[k+2] + h1.w*whh[k+3];
            }
#pragma unroll
            for (int k = WREG; k < Hq; k += 4) {
                float4 h0 = *reinterpret_cast<const float4*>(&sm->sH[k]);
                float4 h1 = *reinterpret_cast<const float4*>(&sm->sH[128 + k]);
                float w0 = __ldg(&Whh[(k + 0) * G3q + tid]);
                float w1 = __ldg(&Whh[(k + 1) * G3q + tid]);
                float w2 = __ldg(&Whh[(k + 2) * G3q + tid]);
                float w3 = __ldg(&Whh[(k + 3) * G3q + tid]);
                acc0 += h0.x*w0 + h0.y*w1 + h0.z*w2 + h0.w*w3;
                acc1 += h1.x*w0 + h1.y*w1 + h1.z*w2 + h1.w*w3;
            }
            sm->sGh[tid]       = acc0;
            sm->sGh[G3q + tid] = acc1;
        }
        __syncthreads();

        // ===== Region B: GRU elementwise (enc finalized per-thread, gi inline) =====
        if (tid < 256) {
            int b = tid >> 7, j = tid & 127;
            float e0 = fmaxf(fmaxf(sm->sEncW[0*2+b], sm->sEncW[1*2+b]),
                             fmaxf(sm->sEncW[2*2+b], sm->sEncW[3*2+b]));
            float e1 = fmaxf(fmaxf(sm->sEncW[4*2+b], sm->sEncW[5*2+b]),
                             fmaxf(sm->sEncW[6*2+b], sm->sEncW[7*2+b]));
            float e2 = fmaxf(fmaxf(sm->sEncW[8*2+b], sm->sEncW[9*2+b]),
                             fmaxf(sm->sEncW[10*2+b], sm->sEncW[11*2+b]));
            float er = sm->sErr[b];
            float gir = sm->sBih[j]
                      + e0 * sm->sWih[j]             + e1 * sm->sWih[G3q + j]
                      + e2 * sm->sWih[2*G3q + j]     + er * sm->sWih[3*G3q + j];
            float giz = sm->sBih[128 + j]
                      + e0 * sm->sWih[128 + j]           + e1 * sm->sWih[G3q + 128 + j]
                      + e2 * sm->sWih[2*G3q + 128 + j]   + er * sm->sWih[3*G3q + 128 + j];
            float gin = sm->sBih[256 + j]
                      + e0 * sm->sWih[256 + j]           + e1 * sm->sWih[G3q + 256 + j]
                      + e2 * sm->sWih[2*G3q + 256 + j]   + er * sm->sWih[3*G3q + 256 + j];
            float ghr = sm->sGh[b * G3q + j];
            float ghz = sm->sGh[b * G3q + 128 + j];
            float ghn = sm->sGh[b * G3q + 256 + j];
            float rr = sigmoid_precise(gir + ghr);
            float zz = sigmoid_precise(giz + ghz);
            float nn = tanhf(gin + rr * ghn);
            float hold = sm->sH[b * 128 + j];
            sm->sH[b * 128 + j] = (1.f - zz) * nn + zz * hold;
        }
        __syncthreads();

        // ===== Region C: logits + softmax + theta mix + penalty (warp b per batch) =====
        if (wid < 2) {
            int b = wid;
            float am0 = 0.f, am1 = 0.f, am2 = 0.f;
#pragma unroll
            for (int kk = 0; kk < 4; kk++) {
                int j = lane + 32 * kk;
                float hv = sm->sH[b * 128 + j];
                am0 += hv * sm->sWdT[j];          // col 127 weight is 0
                am1 += hv * sm->sWdT[128 + j];
                am2 += hv * sm->sWdT[256 + j];
            }
#pragma unroll
            for (int off = 16; off; off >>= 1) {
                am0 += __shfl_xor_sync(0xffffffffu, am0, off);
                am1 += __shfl_xor_sync(0xffffffffu, am1, off);
                am2 += __shfl_xor_sync(0xffffffffu, am2, off);
            }
            if (lane == 0) {
                float l0 = am0 + sm->sBd[0], l1 = am1 + sm->sBd[1], l2 = am2 + sm->sBd[2];
                float mx = fmaxf(l0, fmaxf(l1, l2));
                float e0 = expf(l0 - mx), e1 = expf(l1 - mx), e2 = expf(l2 - mx);
                float inv = 1.f / (e0 + e1 + e2);
                float theta = sigmoid_precise(sm->sH[b * 128 + 127]);
                float omt = 1.f - theta;
                float g0 = e0 * inv * theta + sm->sGate[b * 4]     * omt;
                float g1 = e1 * inv * theta + sm->sGate[b * 4 + 1] * omt;
                float g2 = e2 * inv * theta + sm->sGate[b * 4 + 2] * omt;
                sm->sGate[b * 4]     = g0;
                sm->sGate[b * 4 + 1] = g1;
                sm->sGate[b * 4 + 2] = g2;
                float pen = g0 * (1.f - g0) + g1 * (1.f - g1) + g2 * (1.f - g2);
                out[BT_TOT + (size_t)(b0 + b) * Tq + t] = pen;
            }
        }
        __syncthreads();

        // ===== Region D: s_new partials = Sum_p (g.K)[p] * A[p][n]; warp owns 64 p's =====
        {
            const int half = lane >> 4, li = lane & 15;   // li -> n = 4*li..4*li+3
            const int pbase = wid * 64;
            float4 ac0 = make_float4(0.f, 0.f, 0.f, 0.f);
            float4 ac1 = make_float4(0.f, 0.f, 0.f, 0.f);
            const float4* A4  = reinterpret_cast<const float4*>(A);
            const float2* K20 = reinterpret_cast<const float2*>(sm->sK);
            const float2* K21 = K20 + 384;
#pragma unroll 8
            for (int i = 0; i < 32; i++) {
                int p = pbase + 2 * i + half;
                float4 av = __ldg(&A4[p * 16 + li]);
                float2 kk0 = K20[(pbase >> 1) + i];
                float2 kk1 = K21[(pbase >> 1) + i];
                float k0 = half ? kk0.y : kk0.x;
                float k1 = half ? kk1.y : kk1.x;
                ac0.x += k0 * av.x; ac0.y += k0 * av.y; ac0.z += k0 * av.z; ac0.w += k0 * av.w;
                ac1.x += k1 * av.x; ac1.y += k1 * av.y; ac1.z += k1 * av.z; ac1.w += k1 * av.w;
            }
            // combine even/odd-p halves
            ac0.x += __shfl_xor_sync(0xffffffffu, ac0.x, 16);
            ac0.y += __shfl_xor_sync(0xffffffffu, ac0.y, 16);
            ac0.z += __shfl_xor_sync(0xffffffffu, ac0.z, 16);
            ac0.w += __shfl_xor_sync(0xffffffffu, ac0.w, 16);
            ac1.x += __shfl_xor_sync(0xffffffffu, ac1.x, 16);
            ac1.y += __shfl_xor_sync(0xffffffffu, ac1.y, 16);
            ac1.z += __shfl_xor_sync(0xffffffffu, ac1.z, 16);
            ac1.w += __shfl_xor_sync(0xffffffffu, ac1.w, 16);
            if (lane < 16) {
                float g0 = sm->sGate[0 + (wid >> 2)];       // batch 0, m = wid/4
                float g1 = sm->sGate[4 + (wid >> 2)];       // batch 1
                float4 r0 = make_float4(g0*ac0.x, g0*ac0.y, g0*ac0.z, g0*ac0.w);
                float4 r1 = make_float4(g1*ac1.x, g1*ac1.y, g1*ac1.z, g1*ac1.w);
                *reinterpret_cast<float4*>(&sm->sRed[wid * 128 +      4 * li]) = r0;
                *reinterpret_cast<float4*>(&sm->sRed[wid * 128 + 64 + 4 * li]) = r1;
            }
        }
        __syncthreads();

        // ===== Region E: reduce partials -> s_new, |s|^2, pred/err; preload x,y =====
        if (tid < 128) {
            float s = 0.f;
#pragma unroll
            for (int w = 0; w < 12; w++) s += sm->sRed[w * 128 + tid];
            sm->sS[tid] = s;
            float sq = s * s;
#pragma unroll
            for (int off = 16; off; off >>= 1)
                sq += __shfl_xor_sync(0xffffffffu, sq, off);
            if (lane == 0) sm->sQpart[wid] = sq;   // warps 0..3
            if ((tid & 63) == 63) {
                int b = tid >> 6, bb = b0 + b;
                out[(size_t)bb * Tq + t] = s;      // pred
                sm->sErr[b] = s - sm->sY[b];
            }
        } else if (t + 1 < Tq) {
            int q2 = tid - 128;
            if (q2 < 8) {
                int b = q2 >> 2, i = q2 & 3;
                sm->sX[b * 4 + i] = x[(size_t)(b0 + b) * Tq * INq + (size_t)(t + 1) * INq + i];
            } else if (q2 < 10) {
                int b = q2 - 8;
                sm->sY[b] = y[(size_t)(b0 + b) * Tq + (t + 1)];
            }
        }
        __syncthreads();
    }
}

extern "C" void kernel_launch(void* const* d_in, const int* in_sizes, int n_in,
                              void* d_out, int out_size) {
    const float* x   = (const float*)d_in[0];
    const float* y   = (const float*)d_in[1];
    const float* U   = (const float*)d_in[2];
    const float* S   = (const float*)d_in[3];
    const float* A   = (const float*)d_in[4];
    const float* Wih = (const float*)d_in[5];
    const float* Whh = (const float*)d_in[6];
    const float* bih = (const float*)d_in[7];
    const float* bhh = (const float*)d_in[8];
    const float* Wd  = (const float*)d_in[9];
    const float* bd  = (const float*)d_in[10];
    float* out = (float*)d_out;

    cudaFuncSetAttribute(scan_kernel, cudaFuncAttributeMaxDynamicSharedMemorySize,
                         (int)sizeof(Smem));

    prep_kernel<<<3, 256>>>(U, S);
    scan_kernel<<<NCTA, NTHR, sizeof(Smem)>>>(x, y, U, A, Whh, Wd, bd, Wih, bih, bhh, out);
}

// round 14
// speedup vs baseline: 2.1309x; 1.0611x over previous
#include <cuda_runtime.h>

// Problem constants
#define Bq    256
#define Tq    512
#define INq   4
#define PAIRS 768      // M*D
#define NSq   64
#define Hq    128
#define G3q   384      // 3*H
#define NTHR  384
#define NCTA  128      // 2 batches per CTA
#define BT_TOT (Bq*Tq)
#define WREG  96       // W_hh rows cached in registers

struct __align__(16) Smem {
    float sST[NSq * PAIRS];   // S transposed: [n][p]
    float sK[2 * PAIRS];      // K values: [b][p] (float2 pairs (2t,2t+1))
    float sGh[2 * G3q];       // gh: [b][col]  (gh for step t, computed at E(t-1))
    float sH[2 * Hq];         // hidden state
    float sS[2 * NSq];        // recurrent state s
    float sWih[4 * G3q];      // W_ih row-major
    float sBih[G3q];
    float sBhh[G3q];
    float sWdT[3 * Hq];       // Wd transposed, padded (col 127 = 0)
    float sRed[12 * 128];     // K.A partials (unscaled): [warp][b*64+n]
    float sEncW[32];          // per-warp K max: [w*2+b] (w<12)
    float sLogW[32];          // logit partials: [w*4+m] (w<8)
    float sQpart[4];          // warp partials of |s|^2
    float sBd[4];
    float sX[8];              // x_t both batches
    float sY[4];              // y, parity double-buffered: [par*2+b]  (RACE FIX)
    float sErr[4];
    float sGate[16];          // gate, parity double-buffered: [par][b*4+m]
};

// Precomputed weight transforms
__device__ __align__(16) float g_ST[NSq * PAIRS];   // [n][p]
__device__ __align__(16) float g_C[PAIRS];          // -0.5*(|U_p|^2+|S_p|^2)

__global__ void prep_kernel(const float* __restrict__ U,
                            const float* __restrict__ S) {
    int p = blockIdx.x * blockDim.x + threadIdx.x;
    if (p >= PAIRS) return;
    float cs = 0.f;
    for (int n = 0; n < NSq; n++) {
        float v = S[p * NSq + n];
        cs += v * v;
        g_ST[n * PAIRS + p] = v;
    }
    float cu = 0.f;
    for (int i = 0; i < INq; i++) { float u = U[p * INq + i]; cu += u * u; }
    g_C[p] = -0.5f * (cu + cs);
}

__device__ __forceinline__ float sigmoid_precise(float v) {
    return 1.f / (1.f + expf(-v));
}

__global__ void __launch_bounds__(NTHR, 1)
scan_kernel(const float* __restrict__ x, const float* __restrict__ y,
            const float* __restrict__ U, const float* __restrict__ A,
            const float* __restrict__ Whh,
            const float* __restrict__ Wd, const float* __restrict__ bd,
            const float* __restrict__ Wih,
            const float* __restrict__ bih, const float* __restrict__ bhh,
            float* __restrict__ out) {
    extern __shared__ float smraw[];
    Smem* sm = reinterpret_cast<Smem*>(smraw);
    const int tid  = threadIdx.x;
    const int wid  = tid >> 5;
    const int lane = tid & 31;
    const int b0   = blockIdx.x * 2;

    // ---- persistent registers: W_hh column (rows 0..WREG-1) for col = tid
    float whh[WREG];
#pragma unroll
    for (int k = 0; k < WREG; k++) whh[k] = Whh[k * G3q + tid];

    // U rows + C for this thread's two adjacent pairs p0=2t, p1=2t+1
    const int p0 = 2 * tid, p1 = 2 * tid + 1;
    float Ua[4], Ub[4];
#pragma unroll
    for (int i = 0; i < 4; i++) { Ua[i] = U[p0 * 4 + i]; Ub[i] = U[p1 * 4 + i]; }
    const float C0 = g_C[p0], C1 = g_C[p1];

    // ---- one-time smem init ----
    {
        const float4* src = reinterpret_cast<const float4*>(g_ST);
        float4* dst = reinterpret_cast<float4*>(sm->sST);
        for (int i = tid; i < (NSq * PAIRS) / 4; i += NTHR) dst[i] = src[i];
    }
    for (int i = tid; i < 4 * G3q; i += NTHR) sm->sWih[i] = Wih[i];
    for (int i = tid; i < G3q; i += NTHR) {
        float v = bhh[i];
        sm->sBih[i] = bih[i];
        sm->sBhh[i] = v;
        sm->sGh[i] = v;           // gh(0): h=0 -> gh = bhh
        sm->sGh[G3q + i] = v;
    }
    for (int i = tid; i < 3 * Hq; i += NTHR) {
        int m = i >> 7, j = i & 127;
        sm->sWdT[m * 128 + j] = (j < 127) ? Wd[j * 3 + m] : 0.f;
    }
    if (tid < 4) sm->sBd[tid] = (tid < 3) ? bd[tid] : 0.f;
    for (int i = tid; i < 2 * NSq; i += NTHR) sm->sS[i] = 0.f;
    for (int i = tid; i < 2 * Hq; i += NTHR) sm->sH[i] = 0.f;
    if (tid < 16) {
        int mm = tid & 3;
        sm->sGate[tid] = (mm == 0) ? 0.3333f : (mm == 1) ? 0.3333f : (mm == 2) ? 0.3334f : 0.f;
    }
    if (tid < 2) sm->sErr[tid] = 1.f;
    if (tid < 4) sm->sQpart[tid] = 0.f;
    if (tid < 8) {
        int b = tid >> 2, i = tid & 3;
        sm->sX[b * 4 + i] = x[(size_t)(b0 + b) * Tq * INq + i];
    }
    if (tid >= 8 && tid < 10) {
        int b = tid - 8;
        sm->sY[0 * 2 + b] = y[(size_t)(b0 + b) * Tq];   // parity 0 slot for t=0
    }
    __syncthreads();

    for (int t = 0; t < Tq; t++) {
        // ===== Region A: K = exp(C + base + x.U + s.S), per-warp enc max =====
        {
            float q0 = sm->sQpart[0] + sm->sQpart[1];
            float q1 = sm->sQpart[2] + sm->sQpart[3];
            float xa0 = sm->sX[0], xa1 = sm->sX[1], xa2 = sm->sX[2], xa3 = sm->sX[3];
            float xb0 = sm->sX[4], xb1 = sm->sX[5], xb2 = sm->sX[6], xb3 = sm->sX[7];
            float base0 = -0.5f * (xa0*xa0 + xa1*xa1 + xa2*xa2 + xa3*xa3 + q0);
            float base1 = -0.5f * (xb0*xb0 + xb1*xb1 + xb2*xb2 + xb3*xb3 + q1);

            float a00 = 0.f, a01 = 0.f, a10 = 0.f, a11 = 0.f;
            const float2* W2 = reinterpret_cast<const float2*>(sm->sST);
#pragma unroll
            for (int n = 0; n < NSq; n += 4) {
                float4 sv0 = *reinterpret_cast<const float4*>(&sm->sS[n]);
                float4 sv1 = *reinterpret_cast<const float4*>(&sm->sS[64 + n]);
                float2 w0 = W2[(n + 0) * 384 + tid];
                float2 w1 = W2[(n + 1) * 384 + tid];
                float2 w2 = W2[(n + 2) * 384 + tid];
                float2 w3 = W2[(n + 3) * 384 + tid];
                a00 += sv0.x*w0.x + sv0.y*w1.x + sv0.z*w2.x + sv0.w*w3.x;
                a10 += sv0.x*w0.y + sv0.y*w1.y + sv0.z*w2.y + sv0.w*w3.y;
                a01 += sv1.x*w0.x + sv1.y*w1.x + sv1.z*w2.x + sv1.w*w3.x;
                a11 += sv1.x*w0.y + sv1.y*w1.y + sv1.z*w2.y + sv1.w*w3.y;
            }
            float xu00 = xa0*Ua[0] + xa1*Ua[1] + xa2*Ua[2] + xa3*Ua[3];
            float xu01 = xb0*Ua[0] + xb1*Ua[1] + xb2*Ua[2] + xb3*Ua[3];
            float xu10 = xa0*Ub[0] + xa1*Ub[1] + xa2*Ub[2] + xa3*Ub[3];
            float xu11 = xb0*Ub[0] + xb1*Ub[1] + xb2*Ub[2] + xb3*Ub[3];
            float k00 = __expf(C0 + base0 + xu00 + a00);
            float k01 = __expf(C0 + base1 + xu01 + a01);
            float k10 = __expf(C1 + base0 + xu10 + a10);
            float k11 = __expf(C1 + base1 + xu11 + a11);
            reinterpret_cast<float2*>(sm->sK)[tid]       = make_float2(k00, k10);
            reinterpret_cast<float2*>(sm->sK)[384 + tid] = make_float2(k01, k11);
            float v0 = fmaxf(k00, k10), v1 = fmaxf(k01, k11);
#pragma unroll
            for (int off = 16; off; off >>= 1) {
                v0 = fmaxf(v0, __shfl_xor_sync(0xffffffffu, v0, off));
                v1 = fmaxf(v1, __shfl_xor_sync(0xffffffffu, v1, off));
            }
            if (lane == 0) { sm->sEncW[wid * 2] = v0; sm->sEncW[wid * 2 + 1] = v1; }
        }
        __syncthreads();

        // ===== Region BD: K.A partials (unscaled, all warps) + GRU + logit partials =====
        {
            const int half = lane >> 4, li = lane & 15;
            const int pbase = wid * 64;
            float4 ac0 = make_float4(0.f, 0.f, 0.f, 0.f);
            float4 ac1 = make_float4(0.f, 0.f, 0.f, 0.f);
            const float4* A4  = reinterpret_cast<const float4*>(A);
            const float2* K20 = reinterpret_cast<const float2*>(sm->sK);
            const float2* K21 = K20 + 384;
#pragma unroll 8
            for (int i = 0; i < 32; i++) {
                int p = pbase + 2 * i + half;
                float4 av = __ldg(&A4[p * 16 + li]);
                float2 kk0 = K20[(pbase >> 1) + i];
                float2 kk1 = K21[(pbase >> 1) + i];
                float k0 = half ? kk0.y : kk0.x;
                float k1 = half ? kk1.y : kk1.x;
                ac0.x += k0 * av.x; ac0.y += k0 * av.y; ac0.z += k0 * av.z; ac0.w += k0 * av.w;
                ac1.x += k1 * av.x; ac1.y += k1 * av.y; ac1.z += k1 * av.z; ac1.w += k1 * av.w;
            }
            ac0.x += __shfl_xor_sync(0xffffffffu, ac0.x, 16);
            ac0.y += __shfl_xor_sync(0xffffffffu, ac0.y, 16);
            ac0.z += __shfl_xor_sync(0xffffffffu, ac0.z, 16);
            ac0.w += __shfl_xor_sync(0xffffffffu, ac0.w, 16);
            ac1.x += __shfl_xor_sync(0xffffffffu, ac1.x, 16);
            ac1.y += __shfl_xor_sync(0xffffffffu, ac1.y, 16);
            ac1.z += __shfl_xor_sync(0xffffffffu, ac1.z, 16);
            ac1.w += __shfl_xor_sync(0xffffffffu, ac1.w, 16);
            if (lane < 16) {
                *reinterpret_cast<float4*>(&sm->sRed[wid * 128 +      4 * li]) = ac0;
                *reinterpret_cast<float4*>(&sm->sRed[wid * 128 + 64 + 4 * li]) = ac1;
            }

            // GRU elementwise + logit partials (threads 0..255; warp covers 32 j's of one b)
            if (tid < 256) {
                int b = tid >> 7, j = tid & 127;
                float e0 = fmaxf(fmaxf(sm->sEncW[0*2+b], sm->sEncW[1*2+b]),
                                 fmaxf(sm->sEncW[2*2+b], sm->sEncW[3*2+b]));
                float e1 = fmaxf(fmaxf(sm->sEncW[4*2+b], sm->sEncW[5*2+b]),
                                 fmaxf(sm->sEncW[6*2+b], sm->sEncW[7*2+b]));
                float e2 = fmaxf(fmaxf(sm->sEncW[8*2+b], sm->sEncW[9*2+b]),
                                 fmaxf(sm->sEncW[10*2+b], sm->sEncW[11*2+b]));
                float er = sm->sErr[b];
                float gir = sm->sBih[j]
                          + e0 * sm->sWih[j]             + e1 * sm->sWih[G3q + j]
                          + e2 * sm->sWih[2*G3q + j]     + er * sm->sWih[3*G3q + j];
                float giz = sm->sBih[128 + j]
                          + e0 * sm->sWih[128 + j]           + e1 * sm->sWih[G3q + 128 + j]
                          + e2 * sm->sWih[2*G3q + 128 + j]   + er * sm->sWih[3*G3q + 128 + j];
                float gin = sm->sBih[256 + j]
                          + e0 * sm->sWih[256 + j]           + e1 * sm->sWih[G3q + 256 + j]
                          + e2 * sm->sWih[2*G3q + 256 + j]   + er * sm->sWih[3*G3q + 256 + j];
                float ghr = sm->sGh[b * G3q + j];
                float ghz = sm->sGh[b * G3q + 128 + j];
                float ghn = sm->sGh[b * G3q + 256 + j];
                float rr = sigmoid_precise(gir + ghr);
                float zz = sigmoid_precise(giz + ghz);
                float nn = tanhf(gin + rr * ghn);
                float hv = (1.f - zz) * nn + zz * sm->sH[b * 128 + j];
                sm->sH[b * 128 + j] = hv;
                // logit partials from the register-resident h
                float lm0 = hv * sm->sWdT[j];          // col 127 weight is 0
                float lm1 = hv * sm->sWdT[128 + j];
                float lm2 = hv * sm->sWdT[256 + j];
#pragma unroll
                for (int off = 16; off; off >>= 1) {
                    lm0 += __shfl_xor_sync(0xffffffffu, lm0, off);
                    lm1 += __shfl_xor_sync(0xffffffffu, lm1, off);
                    lm2 += __shfl_xor_sync(0xffffffffu, lm2, off);
                }
                if (lane == 0) {
                    sm->sLogW[wid * 4 + 0] = lm0;
                    sm->sLogW[wid * 4 + 1] = lm1;
                    sm->sLogW[wid * 4 + 2] = lm2;
                }
            }
        }
        __syncthreads();

        // ===== Region E: softmax(redundant) + s_new reduce + gh(t+1) GEMV =====
        {
            // gh(t+1) = h(t) @ W_hh + b_hh : all 384 threads, col = tid
            float acc0 = sm->sBhh[tid];
            float acc1 = acc0;
#pragma unroll
            for (int k = 0; k < WREG; k += 4) {
                float4 h0 = *reinterpret_cast<const float4*>(&sm->sH[k]);
                float4 h1 = *reinterpret_cast<const float4*>(&sm->sH[128 + k]);
                acc0 += h0.x*whh[k] + h0.y*whh[k+1] + h0.z*whh[k+2] + h0.w*whh[k+3];
                acc1 += h1.x*whh[k] + h1.y*whh[k+1] + h1.z*whh[k+2] + h1.w*whh[k+3];
            }
#pragma unroll
            for (int k = WREG; k < Hq; k += 4) {
                float4 h0 = *reinterpret_cast<const float4*>(&sm->sH[k]);
                float4 h1 = *reinterpret_cast<const float4*>(&sm->sH[128 + k]);
                float w0 = __ldg(&Whh[(k + 0) * G3q + tid]);
                float w1 = __ldg(&Whh[(k + 1) * G3q + tid]);
                float w2 = __ldg(&Whh[(k + 2) * G3q + tid]);
                float w3 = __ldg(&Whh[(k + 3) * G3q + tid]);
                acc0 += h0.x*w0 + h0.y*w1 + h0.z*w2 + h0.w*w3;
                acc1 += h1.x*w0 + h1.y*w1 + h1.z*w2 + h1.w*w3;
            }
            sm->sGh[tid]       = acc0;
            sm->sGh[G3q + tid] = acc1;

            if (tid < 128) {
                int b = tid >> 6, n = tid & 63;
                // per-m sums over the 4 warps of each m
                float ns0 = sm->sRed[0*128 + tid] + sm->sRed[1*128 + tid]
                          + sm->sRed[2*128 + tid] + sm->sRed[3*128 + tid];
                float ns1 = sm->sRed[4*128 + tid] + sm->sRed[5*128 + tid]
                          + sm->sRed[6*128 + tid] + sm->sRed[7*128 + tid];
                float ns2 = sm->sRed[8*128 + tid] + sm->sRed[9*128 + tid]
                          + sm->sRed[10*128 + tid] + sm->sRed[11*128 + tid];
                // redundant gate computation (broadcast reads, fully parallel)
                float l0 = sm->sBd[0] + sm->sLogW[(b*4+0)*4+0] + sm->sLogW[(b*4+1)*4+0]
                                      + sm->sLogW[(b*4+2)*4+0] + sm->sLogW[(b*4+3)*4+0];
                float l1 = sm->sBd[1] + sm->sLogW[(b*4+0)*4+1] + sm->sLogW[(b*4+1)*4+1]
                                      + sm->sLogW[(b*4+2)*4+1] + sm->sLogW[(b*4+3)*4+1];
                float l2 = sm->sBd[2] + sm->sLogW[(b*4+0)*4+2] + sm->sLogW[(b*4+1)*4+2]
                                      + sm->sLogW[(b*4+2)*4+2] + sm->sLogW[(b*4+3)*4+2];
                float mx = fmaxf(l0, fmaxf(l1, l2));
                float e0 = expf(l0 - mx), e1 = expf(l1 - mx), e2 = expf(l2 - mx);
                float inv = 1.f / (e0 + e1 + e2);
                float theta = sigmoid_precise(sm->sH[b * 128 + 127]);
                float omt = 1.f - theta;
                int par = t & 1;
                float g0 = e0 * inv * theta + sm->sGate[par * 8 + b * 4 + 0] * omt;
                float g1 = e1 * inv * theta + sm->sGate[par * 8 + b * 4 + 1] * omt;
                float g2 = e2 * inv * theta + sm->sGate[par * 8 + b * 4 + 2] * omt;
                float s = g0 * ns0 + g1 * ns1 + g2 * ns2;
                sm->sS[tid] = s;
                float sq = s * s;
#pragma unroll
                for (int off = 16; off; off >>= 1)
                    sq += __shfl_xor_sync(0xffffffffu, sq, off);
                if (lane == 0) sm->sQpart[wid] = sq;
                if (n == 0) {
                    int np = par ^ 1;
                    sm->sGate[np * 8 + b * 4 + 0] = g0;
                    sm->sGate[np * 8 + b * 4 + 1] = g1;
                    sm->sGate[np * 8 + b * 4 + 2] = g2;
                    float pen = g0 * (1.f - g0) + g1 * (1.f - g1) + g2 * (1.f - g2);
                    out[BT_TOT + (size_t)(b0 + b) * Tq + t] = pen;
                }
                if (n == 63) {
                    out[(size_t)(b0 + b) * Tq + t] = s;   // pred
                    // RACE FIX: read this step's y from the parity slot; writers
                    // below fill the OTHER parity slot for t+1.
                    sm->sErr[b] = s - sm->sY[(t & 1) * 2 + b];
                }
            } else if (t + 1 < Tq) {
                int q2 = tid - 128;
                if (q2 < 8) {
                    int b = q2 >> 2, i = q2 & 3;
                    sm->sX[b * 4 + i] = x[(size_t)(b0 + b) * Tq * INq + (size_t)(t + 1) * INq + i];
                } else if (q2 < 10) {
                    int b = q2 - 8;
                    sm->sY[((t + 1) & 1) * 2 + b] = y[(size_t)(b0 + b) * Tq + (t + 1)];
                }
            }
        }
        __syncthreads();
    }
}

extern "C" void kernel_launch(void* const* d_in, const int* in_sizes, int n_in,
                              void* d_out, int out_size) {
    const float* x   = (const float*)d_in[0];
    const float* y   = (const float*)d_in[1];
    const float* U   = (const float*)d_in[2];
    const float* S   = (const float*)d_in[3];
    const float* A   = (const float*)d_in[4];
    const float* Wih = (const float*)d_in[5];
    const float* Whh = (const float*)d_in[6];
    const float* bih = (const float*)d_in[7];
    const float* bhh = (const float*)d_in[8];
    const float* Wd  = (const float*)d_in[9];
    const float* bd  = (const float*)d_in[10];
    float* out = (float*)d_out;

    cudaFuncSetAttribute(scan_kernel, cudaFuncAttributeMaxDynamicSharedMemorySize,
                         (int)sizeof(Smem));

    prep_kernel<<<3, 256>>>(U, S);
    scan_kernel<<<NCTA, NTHR, sizeof(Smem)>>>(x, y, U, A, Whh, Wd, bd, Wih, bih, bhh, out);
}